// round 1
// baseline (speedup 1.0000x reference)
#include <cuda_runtime.h>
#include <math.h>

#define TT 4096
#define NB 2
#define NC 32
#define PAD 132

// ---------------- static device scratch (no allocations allowed) ----------
__device__ float g_tokens[NB*TT*128];
__device__ float g_x[NB*TT*128];
__device__ float g_P[(size_t)NB*TT*512];
__device__ float g_Qp[NB*TT*128];
__device__ float g_Kp[NB*TT*128];
__device__ float g_Vg[NB*TT*128];
__device__ float g_KV[NB*NC*128*128];
__device__ float g_S[NB*NC*128*128];
__device__ float g_Ksum[NB*NC*128];
__device__ float g_KsumX[NB*NC*128];
__device__ float g_A[(size_t)NB*TT*128];   // masked scores [b][t][s_in_chunk]
__device__ float g_den[NB*TT];
__device__ float g_attn[NB*TT*128];
__device__ float g_y[NB*TT*128];
__device__ float g_Wcat[2*512*128];

// ---------------- helpers ----------------
__device__ __forceinline__ float phi_f(float x){ return x > 0.f ? x + 1.f : expf(x); }
__device__ __forceinline__ float sigm_f(float x){ return 1.f/(1.f+expf(-x)); }

// load a [128 rows x 32 cols] tile (row-major, stride ld) transposed into S[k][m]
__device__ __forceinline__ void loadT(const float* __restrict__ G, int ld,
                                      float (*S)[PAD], int tid){
#pragma unroll
  for(int i=0;i<4;i++){
    int r=(tid>>3)+32*i, kq=(tid&7)<<2;
    float4 v=*(const float4*)(G+(size_t)r*ld+kq);
    S[kq+0][r]=v.x; S[kq+1][r]=v.y; S[kq+2][r]=v.z; S[kq+3][r]=v.w;
  }
}
// load a [32 rows x 128 cols] tile (row-major, stride ld) directly into S[k][n]
__device__ __forceinline__ void loadD(const float* __restrict__ G, int ld,
                                      float (*S)[PAD], int tid){
#pragma unroll
  for(int i=0;i<4;i++){
    int r=(tid>>5)+8*i, c=(tid&31)<<2;
    *(float4*)&S[r][c] = *(const float4*)(G+(size_t)r*ld+c);
  }
}
__device__ __forceinline__ void mma32(const float (*As)[PAD], const float (*Bs)[PAD],
                                      float acc[8][8], int tx, int ty){
#pragma unroll
  for(int k=0;k<32;k++){
    float a[8], b[8];
    *(float4*)(a  ) = *(const float4*)&As[k][ty*8];
    *(float4*)(a+4) = *(const float4*)&As[k][ty*8+4];
    *(float4*)(b  ) = *(const float4*)&Bs[k][tx*8];
    *(float4*)(b+4) = *(const float4*)&Bs[k][tx*8+4];
#pragma unroll
    for(int i=0;i<8;i++)
#pragma unroll
      for(int j=0;j<8;j++) acc[i][j] += a[i]*b[j];
  }
}

__device__ __forceinline__ float2 block_reduce2(float s, float q){
#pragma unroll
  for(int o=16;o>0;o>>=1){
    s += __shfl_down_sync(0xffffffffu, s, o);
    q += __shfl_down_sync(0xffffffffu, q, o);
  }
  __shared__ float rs[4], rq[4];
  int w = threadIdx.x>>5;
  if((threadIdx.x&31)==0){ rs[w]=s; rq[w]=q; }
  __syncthreads();
  float2 r; r.x = rs[0]+rs[1]+rs[2]+rs[3]; r.y = rq[0]+rq[1]+rq[2]+rq[3];
  return r;
}
__device__ __forceinline__ float block_reduce1(float s){
#pragma unroll
  for(int o=16;o>0;o>>=1) s += __shfl_down_sync(0xffffffffu, s, o);
  __shared__ float rr[4];
  int w = threadIdx.x>>5;
  if((threadIdx.x&31)==0) rr[w]=s;
  __syncthreads();
  return rr[0]+rr[1]+rr[2]+rr[3];
}

// ---------------- setup kernels ----------------
__global__ void build_tokens_k(const float* __restrict__ xs,
                               const float* __restrict__ ys,
                               const float* __restrict__ qx){
  int idx = blockIdx.x*256 + threadIdx.x;         // over NB*TT*128
  int b = idx >> 19;                               // 4096*128 = 2^19
  int r = idx & ((1<<19)-1);
  int t = r >> 7, d = r & 127;
  float v;
  if(t < 4095){
    v = (d < 127) ? xs[((size_t)b*4095 + t)*127 + d] : ys[(size_t)b*4095 + t];
  }else{
    v = (d < 127) ? qx[(size_t)b*127 + d] : 0.f;
  }
  g_tokens[idx] = v;
}

__global__ void build_wcat_k(const float* __restrict__ Wq, const float* __restrict__ Wk,
                             const float* __restrict__ Wv, const float* __restrict__ Wg){
  int idx = blockIdx.x*256 + threadIdx.x;          // over 2*512*128
  int l = idx >> 16;                               // 512*128 = 2^16
  int r = idx & ((1<<16)-1);
  int n = r >> 7, k = r & 127;
  float v = 0.f;
  if(n < 127)            v = Wq[((size_t)l*127 + n)*128 + k];
  else if(n == 127)      v = 0.f;
  else if(n < 255)       v = Wk[((size_t)l*127 + (n-128))*128 + k];
  else if(n == 255)      v = 0.f;
  else if(n < 384)       v = Wv[((size_t)l*128 + (n-256))*128 + k];
  else                   v = Wg[((size_t)l*128 + (n-384))*128 + k];
  g_Wcat[idx] = v;
}

// ---------------- per-layer kernels ----------------
__global__ void ln1_kernel(const float* __restrict__ w, const float* __restrict__ bia){
  int t = blockIdx.x, b = blockIdx.y, h = threadIdx.x;
  size_t idx = ((size_t)b*TT + t)*128 + h;
  float x = g_tokens[idx];
  float2 r = block_reduce2(x, x*x);
  float m = r.x * (1.f/128.f);
  float var = r.y * (1.f/128.f) - m*m;
  g_x[idx] = (x - m) * rsqrtf(var + 1e-5f) * w[h] + bia[h];
}

// P[8192 x 512] = x[8192 x 128] @ Wcat[l]^T
__global__ void proj_kernel(int l){
  __shared__ float As[32][PAD], Bs[32][PAD];
  int tid=threadIdx.x, tx=tid&15, ty=tid>>4;
  const float* A  = g_x    + (size_t)blockIdx.x*128*128;
  const float* Bp = g_Wcat + (size_t)l*512*128 + (size_t)blockIdx.y*128*128;
  float acc[8][8];
#pragma unroll
  for(int i=0;i<8;i++)
#pragma unroll
    for(int j=0;j<8;j++) acc[i][j]=0.f;
  for(int k0=0;k0<128;k0+=32){
    loadT(A +k0,128,As,tid);
    loadT(Bp+k0,128,Bs,tid);
    __syncthreads();
    mma32(As,Bs,acc,tx,ty);
    __syncthreads();
  }
  float* C = g_P + (size_t)blockIdx.x*128*512 + blockIdx.y*128;
#pragma unroll
  for(int i=0;i<8;i++)
#pragma unroll
    for(int j=0;j<8;j++) C[(size_t)(ty*8+i)*512 + tx*8+j] = acc[i][j];
}

__global__ void act_kernel(const float* __restrict__ gb){
  int t = blockIdx.x, b = blockIdx.y, h = threadIdx.x;
  size_t bt = (size_t)b*TT + t;
  const float* p = g_P + bt*512;
  size_t o = bt*128 + h;
  float q = p[h], k = p[128+h], v = p[256+h], g = p[384+h] + gb[h];
  g_Qp[o] = (h < 127) ? phi_f(q) : 0.f;
  g_Kp[o] = (h < 127) ? phi_f(k) : 0.f;
  g_Vg[o] = v * sigm_f(g);
}

// per-chunk: KV = Kp_c^T @ Vg_c, Ksum = colsum(Kp_c)
__global__ void kv_kernel(){
  __shared__ float As[32][PAD], Bs[32][PAD];
  int c=blockIdx.x, b=blockIdx.y, tid=threadIdx.x, tx=tid&15, ty=tid>>4;
  size_t base = ((size_t)b*TT + c*128)*128;
  float acc[8][8];
#pragma unroll
  for(int i=0;i<8;i++)
#pragma unroll
    for(int j=0;j<8;j++) acc[i][j]=0.f;
  float ks = 0.f;
  for(int k0=0;k0<128;k0+=32){
    loadD(g_Kp + base + (size_t)k0*128, 128, As, tid);   // As[t][h]
    loadD(g_Vg + base + (size_t)k0*128, 128, Bs, tid);   // Bs[t][m]
    __syncthreads();
    mma32(As,Bs,acc,tx,ty);
    if(tid < 128){
#pragma unroll
      for(int t=0;t<32;t++) ks += As[t][tid];
    }
    __syncthreads();
  }
  size_t ko = (size_t)(b*NC + c)*128*128;
#pragma unroll
  for(int i=0;i<8;i++)
#pragma unroll
    for(int j=0;j<8;j++)
      g_KV[ko + (size_t)(ty*8+i)*128 + tx*8+j] = acc[i][j];
  if(tid < 128) g_Ksum[(size_t)(b*NC + c)*128 + tid] = ks;
}

// exclusive prefix over chunks
__global__ void scan_kernel(){
  int h = blockIdx.x, b = blockIdx.y, m = threadIdx.x;
  float acc = 0.f, ks = 0.f;
  for(int c=0;c<NC;c++){
    size_t i = ((size_t)(b*NC + c)*128 + h)*128 + m;
    g_S[i] = acc;
    acc += g_KV[i];
    if(m == 0){
      size_t j = (size_t)(b*NC + c)*128 + h;
      g_KsumX[j] = ks;
      ks += g_Ksum[j];
    }
  }
}

// masked intra-chunk scores: A = tril(Qp_c @ Kp_c^T)
__global__ void score_kernel(){
  __shared__ float As[32][PAD], Bs[32][PAD];
  int c=blockIdx.x, b=blockIdx.y, tid=threadIdx.x, tx=tid&15, ty=tid>>4;
  size_t base = ((size_t)b*TT + c*128)*128;
  float acc[8][8];
#pragma unroll
  for(int i=0;i<8;i++)
#pragma unroll
    for(int j=0;j<8;j++) acc[i][j]=0.f;
  for(int k0=0;k0<128;k0+=32){
    loadT(g_Qp + base + k0, 128, As, tid);
    loadT(g_Kp + base + k0, 128, Bs, tid);
    __syncthreads();
    mma32(As,Bs,acc,tx,ty);
    __syncthreads();
  }
#pragma unroll
  for(int i=0;i<8;i++)
#pragma unroll
    for(int j=0;j<8;j++){
      int t = ty*8+i, s = tx*8+j;
      g_A[base + (size_t)t*128 + s] = (s <= t) ? acc[i][j] : 0.f;
    }
}

// denom[t] = max(rowsum(A[t]) + Qp[t].KsumX, eps)
__global__ void den_kernel(){
  int t = blockIdx.x, b = blockIdx.y, s = threadIdx.x;
  int c = t >> 7;
  size_t bt = (size_t)b*TT + t;
  float v = g_A[bt*128 + s] + g_Qp[bt*128 + s] * g_KsumX[(size_t)(b*NC + c)*128 + s];
  float tot = block_reduce1(v);
  if(s == 0) g_den[bt] = fmaxf(tot, 1e-6f);
}

// attn = (A @ Vg_c + Qp_c @ S_excl) / den
__global__ void num_kernel(){
  __shared__ float As[32][PAD], Bs[32][PAD];
  int c=blockIdx.x, b=blockIdx.y, tid=threadIdx.x, tx=tid&15, ty=tid>>4;
  size_t base = ((size_t)b*TT + c*128)*128;
  size_t so   = (size_t)(b*NC + c)*128*128;
  float acc[8][8];
#pragma unroll
  for(int i=0;i<8;i++)
#pragma unroll
    for(int j=0;j<8;j++) acc[i][j]=0.f;
  for(int k0=0;k0<128;k0+=32){      // intra-chunk: A[t][s] * Vg[s][m]
    loadT(g_A  + base + k0, 128, As, tid);
    loadD(g_Vg + base + (size_t)k0*128, 128, Bs, tid);
    __syncthreads();
    mma32(As,Bs,acc,tx,ty);
    __syncthreads();
  }
  for(int k0=0;k0<128;k0+=32){      // cross-chunk: Qp[t][h] * S[h][m]
    loadT(g_Qp + base + k0, 128, As, tid);
    loadD(g_S  + so + (size_t)k0*128, 128, Bs, tid);
    __syncthreads();
    mma32(As,Bs,acc,tx,ty);
    __syncthreads();
  }
#pragma unroll
  for(int i=0;i<8;i++){
    int t = ty*8+i;
    float d = g_den[(size_t)b*TT + c*128 + t];
    float inv = 1.f / d;
#pragma unroll
    for(int j=0;j<8;j++)
      g_attn[base + (size_t)t*128 + tx*8+j] = acc[i][j] * inv;
  }
}

// y = attn @ Wo^T
__global__ void wo_kernel(const float* __restrict__ Wo){
  __shared__ float As[32][PAD], Bs[32][PAD];
  int tid=threadIdx.x, tx=tid&15, ty=tid>>4;
  const float* A = g_attn + (size_t)blockIdx.x*128*128;
  float acc[8][8];
#pragma unroll
  for(int i=0;i<8;i++)
#pragma unroll
    for(int j=0;j<8;j++) acc[i][j]=0.f;
  for(int k0=0;k0<128;k0+=32){
    loadT(A  + k0, 128, As, tid);
    loadT(Wo + k0, 128, Bs, tid);
    __syncthreads();
    mma32(As,Bs,acc,tx,ty);
    __syncthreads();
  }
  float* C = g_y + (size_t)blockIdx.x*128*128;
#pragma unroll
  for(int i=0;i<8;i++)
#pragma unroll
    for(int j=0;j<8;j++) C[(size_t)(ty*8+i)*128 + tx*8+j] = acc[i][j];
}

// tokens = LN2(tokens + 0.1*y)
__global__ void ln2res_kernel(const float* __restrict__ w, const float* __restrict__ bia){
  int t = blockIdx.x, b = blockIdx.y, h = threadIdx.x;
  size_t idx = ((size_t)b*TT + t)*128 + h;
  float x = g_tokens[idx] + 0.1f * g_y[idx];
  float2 r = block_reduce2(x, x*x);
  float m = r.x * (1.f/128.f);
  float var = r.y * (1.f/128.f) - m*m;
  g_tokens[idx] = (x - m) * rsqrtf(var + 1e-5f) * w[h] + bia[h];
}

__global__ void pred_kernel(const float* __restrict__ pw, float* __restrict__ out){
  int b = blockIdx.x, h = threadIdx.x;
  float v = g_tokens[((size_t)b*TT + (TT-1))*128 + h] * pw[h];
  float tot = block_reduce1(v);
  if(h == 0) out[b] = tot;
}

// ---------------- launch ----------------
extern "C" void kernel_launch(void* const* d_in, const int* in_sizes, int n_in,
                              void* d_out, int out_size){
  const float* xs   = (const float*)d_in[0];
  const float* ys   = (const float*)d_in[1];
  const float* qx   = (const float*)d_in[2];
  const float* Wq   = (const float*)d_in[3];
  const float* Wk   = (const float*)d_in[4];
  const float* Wv   = (const float*)d_in[5];
  const float* Wgw  = (const float*)d_in[6];
  const float* Wgb  = (const float*)d_in[7];
  const float* Wo   = (const float*)d_in[8];
  const float* ln1w = (const float*)d_in[9];
  const float* ln1b = (const float*)d_in[10];
  const float* ln2w = (const float*)d_in[11];
  const float* ln2b = (const float*)d_in[12];
  const float* pw   = (const float*)d_in[13];
  float* out = (float*)d_out;

  build_wcat_k<<<512, 256>>>(Wq, Wk, Wv, Wgw);
  build_tokens_k<<<4096, 256>>>(xs, ys, qx);

  for(int l=0;l<2;l++){
    ln1_kernel   <<<dim3(TT,NB), 128>>>(ln1w + l*128, ln1b + l*128);
    proj_kernel  <<<dim3(64,4),  256>>>(l);
    act_kernel   <<<dim3(TT,NB), 128>>>(Wgb + l*128);
    kv_kernel    <<<dim3(NC,NB), 256>>>();
    scan_kernel  <<<dim3(128,NB),128>>>();
    score_kernel <<<dim3(NC,NB), 256>>>();
    den_kernel   <<<dim3(TT,NB), 128>>>();
    num_kernel   <<<dim3(NC,NB), 256>>>();
    wo_kernel    <<<dim3(64,1),  256>>>(Wo + (size_t)l*128*128);
    ln2res_kernel<<<dim3(TT,NB), 128>>>(ln2w + l*128, ln2b + l*128);
  }
  pred_kernel<<<NB, 128>>>(pw, out);
}

// round 2
// speedup vs baseline: 1.5214x; 1.5214x over previous
#include <cuda_runtime.h>
#include <cuda_bf16.h>
#include <math.h>

#define TT 4096
#define NB 2
#define NC 32
#define AKP 24   // smem row stride in halves (48B: 16B-aligned rows, ldmatrix conflict-free)

typedef __nv_bfloat16  bf;
typedef __nv_bfloat162 bf2;

// ----------------- static device scratch -----------------
__device__ __align__(16) float g_tokens[NB*TT*128];
__device__ __align__(16) float g_P[(size_t)NB*TT*512];
__device__ __align__(16) float g_KV[NB*NC*128*128];
__device__ __align__(16) float g_Ksum[NB*NC*128];
__device__ __align__(16) float g_KsumX[NB*NC*128];
__device__ __align__(16) float g_den[NB*TT];

__device__ __align__(16) bf g_x_h [NB*TT*128], g_x_l [NB*TT*128];
__device__ __align__(16) bf g_Qp_h[NB*TT*128], g_Qp_l[NB*TT*128];
__device__ __align__(16) bf g_Kp_h[NB*TT*128], g_Kp_l[NB*TT*128];
__device__ __align__(16) bf g_Vg_h[NB*TT*128], g_Vg_l[NB*TT*128];
__device__ __align__(16) bf g_As_h[NB*TT*128], g_As_l[NB*TT*128];
__device__ __align__(16) bf g_S_h [NB*NC*128*128], g_S_l [NB*NC*128*128];
__device__ __align__(16) bf g_at_h[NB*TT*128], g_at_l[NB*TT*128];
__device__ __align__(16) bf g_Wc_h[2*512*128],  g_Wc_l[2*512*128];
__device__ __align__(16) bf g_Wo_h[2*128*128],  g_Wo_l[2*128*128];

// ----------------- helpers -----------------
__device__ __forceinline__ float phi_f(float x){ return x > 0.f ? x + 1.f : expf(x); }
__device__ __forceinline__ float sigm_f(float x){ return 1.f/(1.f+expf(-x)); }
__device__ __forceinline__ float bsum(bf h, bf l){ return __bfloat162float(h)+__bfloat162float(l); }

__device__ __forceinline__ void split1(float v, bf* H, bf* L){
  bf h = __float2bfloat16(v);
  *H = h; *L = __float2bfloat16(v - __bfloat162float(h));
}
__device__ __forceinline__ bf2 split2(float v0, float v1, bf2* lo){
  bf h0=__float2bfloat16(v0), h1=__float2bfloat16(v1);
  *lo = __halves2bfloat162(__float2bfloat16(v0-__bfloat162float(h0)),
                           __float2bfloat16(v1-__bfloat162float(h1)));
  return __halves2bfloat162(h0,h1);
}

__device__ __forceinline__ unsigned sptr(const void* p){
  return (unsigned)__cvta_generic_to_shared(p);
}
__device__ __forceinline__ void ldsm4(unsigned addr, unsigned* r){
  asm volatile("ldmatrix.sync.aligned.m8n8.x4.shared.b16 {%0,%1,%2,%3}, [%4];"
    : "=r"(r[0]),"=r"(r[1]),"=r"(r[2]),"=r"(r[3]) : "r"(addr));
}
__device__ __forceinline__ void mmab(float* c, const unsigned* a, unsigned b0, unsigned b1){
  asm volatile("mma.sync.aligned.m16n8k16.row.col.f32.bf16.bf16.f32 "
    "{%0,%1,%2,%3},{%4,%5,%6,%7},{%8,%9},{%0,%1,%2,%3};"
    : "+f"(c[0]),"+f"(c[1]),"+f"(c[2]),"+f"(c[3])
    : "r"(a[0]),"r"(a[1]),"r"(a[2]),"r"(a[3]),"r"(b0),"r"(b1));
}

__device__ __forceinline__ float2 block_reduce2(float s, float q){
#pragma unroll
  for(int o=16;o>0;o>>=1){
    s += __shfl_down_sync(0xffffffffu, s, o);
    q += __shfl_down_sync(0xffffffffu, q, o);
  }
  __shared__ float rs[4], rq[4];
  int w = threadIdx.x>>5;
  if((threadIdx.x&31)==0){ rs[w]=s; rq[w]=q; }
  __syncthreads();
  float2 r; r.x = rs[0]+rs[1]+rs[2]+rs[3]; r.y = rq[0]+rq[1]+rq[2]+rq[3];
  return r;
}
__device__ __forceinline__ float block_reduce1(float s){
#pragma unroll
  for(int o=16;o>0;o>>=1) s += __shfl_down_sync(0xffffffffu, s, o);
  __shared__ float rr[4];
  int w = threadIdx.x>>5;
  if((threadIdx.x&31)==0) rr[w]=s;
  __syncthreads();
  return rr[0]+rr[1]+rr[2]+rr[3];
}

// ---------- smem tile loaders (256 threads) ----------
// natural: gmem [row][k] bf16 (ldg multiple of 8) -> smem [row][k16]
__device__ __forceinline__ void load_nat(const bf* __restrict__ Gh, const bf* __restrict__ Gl,
                                         size_t base, int ldg, int k0,
                                         bf (*Sh)[AKP], bf (*Sl)[AKP], int tid){
  int r = tid>>1, q = (tid&1)<<3;
  size_t off = base + (size_t)r*ldg + k0 + q;
  *(uint4*)&Sh[r][q] = *(const uint4*)(Gh + off);
  *(uint4*)&Sl[r][q] = *(const uint4*)(Gl + off);
}
// transpose: gmem [k][n] bf16 -> smem [n][k16]
__device__ __forceinline__ void load_trans(const bf* __restrict__ Gh, const bf* __restrict__ Gl,
                                           size_t base, int ldg, int k0,
                                           bf (*Sh)[AKP], bf (*Sl)[AKP], int tid){
  int n = (tid&63)<<1, p0 = tid>>6;
#pragma unroll
  for(int p=p0;p<8;p+=4){
    int k = k0 + 2*p;
    size_t o0 = base + (size_t)k*ldg + n;
    bf2 h0 = *(const bf2*)(Gh + o0);
    bf2 h1 = *(const bf2*)(Gh + o0 + ldg);
    *(bf2*)&Sh[n  ][2*p] = __halves2bfloat162(h0.x, h1.x);
    *(bf2*)&Sh[n+1][2*p] = __halves2bfloat162(h0.y, h1.y);
    bf2 l0 = *(const bf2*)(Gl + o0);
    bf2 l1 = *(const bf2*)(Gl + o0 + ldg);
    *(bf2*)&Sl[n  ][2*p] = __halves2bfloat162(l0.x, l1.x);
    *(bf2*)&Sl[n+1][2*p] = __halves2bfloat162(l0.y, l1.y);
  }
}

// ---------- one k16 stage of bf16x3 mma (per warp: 32x64 tile) ----------
__device__ __forceinline__ void mma_stage(const bf (*AhS)[AKP], const bf (*AlS)[AKP],
                                          const bf (*BhS)[AKP], const bf (*BlS)[AKP],
                                          float acc[2][8][4], int wm, int wn, int lane){
  unsigned ah[2][4], al[2][4];
  int ar = lane & 15, ac = (lane & 16) >> 1;   // 0 or 8
#pragma unroll
  for(int mt=0;mt<2;mt++){
    int r = wm*32 + mt*16 + ar;
    ldsm4(sptr(&AhS[r][ac]), ah[mt]);
    ldsm4(sptr(&AlS[r][ac]), al[mt]);
  }
  int br = (lane&7) + ((lane>>1)&8);
  int bc = lane & 8;
#pragma unroll
  for(int p=0;p<4;p++){
    unsigned bh[4], bl[4];
    int n = wn*64 + p*16 + br;
    ldsm4(sptr(&BhS[n][bc]), bh);
    ldsm4(sptr(&BlS[n][bc]), bl);
#pragma unroll
    for(int mt=0;mt<2;mt++){
      mmab(acc[mt][2*p  ], ah[mt], bh[0],bh[1]);
      mmab(acc[mt][2*p  ], al[mt], bh[0],bh[1]);
      mmab(acc[mt][2*p  ], ah[mt], bl[0],bl[1]);
      mmab(acc[mt][2*p+1], ah[mt], bh[2],bh[3]);
      mmab(acc[mt][2*p+1], al[mt], bh[2],bh[3]);
      mmab(acc[mt][2*p+1], ah[mt], bl[2],bl[3]);
    }
  }
}

#define GEMM_PRE() \
  __shared__ __align__(16) bf Ah[128][AKP], Al[128][AKP], Bh[128][AKP], Bl[128][AKP]; \
  int tid=threadIdx.x, lane=tid&31, wid=tid>>5; \
  int wm=wid>>1, wn=wid&1; \
  float acc[2][8][4]; \
  _Pragma("unroll") for(int i=0;i<2;i++) _Pragma("unroll") for(int j=0;j<8;j++) \
    _Pragma("unroll") for(int k=0;k<4;k++) acc[i][j][k]=0.f; \
  int gid=lane>>2, tig=lane&3;

// ----------------- setup kernels -----------------
__global__ void build_tokens_k(const float* __restrict__ xs,
                               const float* __restrict__ ys,
                               const float* __restrict__ qx){
  int idx = blockIdx.x*256 + threadIdx.x;
  int b = idx >> 19;
  int r = idx & ((1<<19)-1);
  int t = r >> 7, d = r & 127;
  float v;
  if(t < 4095){
    v = (d < 127) ? xs[((size_t)b*4095 + t)*127 + d] : ys[(size_t)b*4095 + t];
  }else{
    v = (d < 127) ? qx[(size_t)b*127 + d] : 0.f;
  }
  g_tokens[idx] = v;
}

__global__ void build_wcat_k(const float* __restrict__ Wq, const float* __restrict__ Wk,
                             const float* __restrict__ Wv, const float* __restrict__ Wg){
  int idx = blockIdx.x*256 + threadIdx.x;     // 2*512*128
  int l = idx >> 16;
  int r = idx & ((1<<16)-1);
  int n = r >> 7, k = r & 127;
  float v = 0.f;
  if(n < 127)        v = Wq[((size_t)l*127 + n)*128 + k];
  else if(n == 127)  v = 0.f;
  else if(n < 255)   v = Wk[((size_t)l*127 + (n-128))*128 + k];
  else if(n == 255)  v = 0.f;
  else if(n < 384)   v = Wv[((size_t)l*128 + (n-256))*128 + k];
  else               v = Wg[((size_t)l*128 + (n-384))*128 + k];
  split1(v, &g_Wc_h[idx], &g_Wc_l[idx]);
}

__global__ void build_wo_k(const float* __restrict__ Wo){
  int idx = blockIdx.x*256 + threadIdx.x;     // 2*128*128
  split1(Wo[idx], &g_Wo_h[idx], &g_Wo_l[idx]);
}

// ----------------- per-layer elementwise -----------------
__global__ void ln1_kernel(const float* __restrict__ w, const float* __restrict__ bia){
  int t = blockIdx.x, b = blockIdx.y, h = threadIdx.x;
  size_t idx = ((size_t)b*TT + t)*128 + h;
  float x = g_tokens[idx];
  float2 r = block_reduce2(x, x*x);
  float m = r.x * (1.f/128.f);
  float var = r.y * (1.f/128.f) - m*m;
  float o = (x - m) * rsqrtf(var + 1e-5f) * w[h] + bia[h];
  split1(o, &g_x_h[idx], &g_x_l[idx]);
}

__global__ void act_kernel(const float* __restrict__ gb){
  int t = blockIdx.x, b = blockIdx.y, h = threadIdx.x;
  size_t bt = (size_t)b*TT + t;
  const float* p = g_P + bt*512;
  size_t o = bt*128 + h;
  float q = p[h], k = p[128+h], v = p[256+h], g = p[384+h] + gb[h];
  float qp = (h < 127) ? phi_f(q) : 0.f;
  float kp = (h < 127) ? phi_f(k) : 0.f;
  float vg = v * sigm_f(g);
  split1(qp, &g_Qp_h[o], &g_Qp_l[o]);
  split1(kp, &g_Kp_h[o], &g_Kp_l[o]);
  split1(vg, &g_Vg_h[o], &g_Vg_l[o]);
}

__global__ void ksum_kernel(){
  int c = blockIdx.x, b = blockIdx.y, h = threadIdx.x;
  size_t base = ((size_t)b*TT + c*128)*128;
  float s = 0.f;
  for(int t=0;t<128;t++) s += bsum(g_Kp_h[base + (size_t)t*128 + h], g_Kp_l[base + (size_t)t*128 + h]);
  g_Ksum[(size_t)(b*NC + c)*128 + h] = s;
}

__global__ void scan_kernel(){
  int h = blockIdx.x, b = blockIdx.y, m = threadIdx.x;
  float acc = 0.f, ks = 0.f;
  for(int c=0;c<NC;c++){
    size_t i = ((size_t)(b*NC + c)*128 + h)*128 + m;
    split1(acc, &g_S_h[i], &g_S_l[i]);
    acc += g_KV[i];
    if(m == 0){
      size_t j = (size_t)(b*NC + c)*128 + h;
      g_KsumX[j] = ks;
      ks += g_Ksum[j];
    }
  }
}

__global__ void den_kernel(){
  int t = blockIdx.x, b = blockIdx.y, s = threadIdx.x;
  int c = t >> 7;
  size_t bt = (size_t)b*TT + t;
  float a  = bsum(g_As_h[bt*128+s], g_As_l[bt*128+s]);
  float qp = bsum(g_Qp_h[bt*128+s], g_Qp_l[bt*128+s]);
  float v = a + qp * g_KsumX[(size_t)(b*NC + c)*128 + s];
  float tot = block_reduce1(v);
  if(s == 0) g_den[bt] = fmaxf(tot, 1e-6f);
}

__global__ void pred_kernel(const float* __restrict__ pw, float* __restrict__ out){
  int b = blockIdx.x, h = threadIdx.x;
  float v = g_tokens[((size_t)b*TT + (TT-1))*128 + h] * pw[h];
  float tot = block_reduce1(v);
  if(h == 0) out[b] = tot;
}

// ----------------- GEMM kernels (bf16x3 tensor-core) -----------------
// P[8192x512] = x @ Wcat^T
__global__ void proj_kernel(int l){
  GEMM_PRE();
  size_t abase = (size_t)blockIdx.x*128*128;
  size_t bbase = ((size_t)l*512 + blockIdx.y*128)*128;
  for(int k0=0;k0<128;k0+=16){
    __syncthreads();
    load_nat(g_x_h,  g_x_l,  abase, 128, k0, Ah, Al, tid);
    load_nat(g_Wc_h, g_Wc_l, bbase, 128, k0, Bh, Bl, tid);
    __syncthreads();
    mma_stage(Ah,Al,Bh,Bl,acc,wm,wn,lane);
  }
  float* C = g_P + (size_t)blockIdx.x*128*512 + blockIdx.y*128;
#pragma unroll
  for(int mt=0;mt<2;mt++){
    int r0 = wm*32+mt*16+gid;
#pragma unroll
    for(int nt=0;nt<8;nt++){
      int col = wn*64+nt*8+tig*2;
      float* a = acc[mt][nt];
      *(float2*)&C[(size_t)r0*512+col]     = make_float2(a[0],a[1]);
      *(float2*)&C[(size_t)(r0+8)*512+col] = make_float2(a[2],a[3]);
    }
  }
}

// KV[h][m] = sum_t Kp[t][h] * Vg[t][m]   (per b,c chunk)
__global__ void kv_kernel(){
  GEMM_PRE();
  int c = blockIdx.x, b = blockIdx.y;
  size_t base = ((size_t)b*TT + c*128)*128;
  for(int k0=0;k0<128;k0+=16){
    __syncthreads();
    load_trans(g_Kp_h, g_Kp_l, base, 128, k0, Ah, Al, tid);
    load_trans(g_Vg_h, g_Vg_l, base, 128, k0, Bh, Bl, tid);
    __syncthreads();
    mma_stage(Ah,Al,Bh,Bl,acc,wm,wn,lane);
  }
  float* C = g_KV + (size_t)(b*NC + c)*16384;
#pragma unroll
  for(int mt=0;mt<2;mt++){
    int r0 = wm*32+mt*16+gid;
#pragma unroll
    for(int nt=0;nt<8;nt++){
      int col = wn*64+nt*8+tig*2;
      float* a = acc[mt][nt];
      *(float2*)&C[(size_t)r0*128+col]     = make_float2(a[0],a[1]);
      *(float2*)&C[(size_t)(r0+8)*128+col] = make_float2(a[2],a[3]);
    }
  }
}

// Asc = tril(Qp @ Kp^T) per chunk
__global__ void score_kernel(){
  GEMM_PRE();
  int c = blockIdx.x, b = blockIdx.y;
  size_t base = ((size_t)b*TT + c*128)*128;
  for(int k0=0;k0<128;k0+=16){
    __syncthreads();
    load_nat(g_Qp_h, g_Qp_l, base, 128, k0, Ah, Al, tid);
    load_nat(g_Kp_h, g_Kp_l, base, 128, k0, Bh, Bl, tid);
    __syncthreads();
    mma_stage(Ah,Al,Bh,Bl,acc,wm,wn,lane);
  }
#pragma unroll
  for(int mt=0;mt<2;mt++){
    int r0 = wm*32+mt*16+gid;
#pragma unroll
    for(int nt=0;nt<8;nt++){
      int col = wn*64+nt*8+tig*2;
      float* a = acc[mt][nt];
      float v0 = (col   <= r0)? a[0] : 0.f;
      float v1 = (col+1 <= r0)? a[1] : 0.f;
      float v2 = (col   <= r0+8)? a[2] : 0.f;
      float v3 = (col+1 <= r0+8)? a[3] : 0.f;
      bf2 lo;
      bf2 hi = split2(v0,v1,&lo);
      *(bf2*)&g_As_h[base + (size_t)r0*128+col] = hi;
      *(bf2*)&g_As_l[base + (size_t)r0*128+col] = lo;
      hi = split2(v2,v3,&lo);
      *(bf2*)&g_As_h[base + (size_t)(r0+8)*128+col] = hi;
      *(bf2*)&g_As_l[base + (size_t)(r0+8)*128+col] = lo;
    }
  }
}

// attn = (Asc @ Vg + Qp @ S) / den   per chunk
__global__ void num_kernel(){
  GEMM_PRE();
  int c = blockIdx.x, b = blockIdx.y;
  size_t base  = ((size_t)b*TT + c*128)*128;
  size_t sbase = (size_t)(b*NC + c)*16384;
  for(int k0=0;k0<128;k0+=16){
    __syncthreads();
    load_nat  (g_As_h, g_As_l, base, 128, k0, Ah, Al, tid);
    load_trans(g_Vg_h, g_Vg_l, base, 128, k0, Bh, Bl, tid);
    __syncthreads();
    mma_stage(Ah,Al,Bh,Bl,acc,wm,wn,lane);
  }
  for(int k0=0;k0<128;k0+=16){
    __syncthreads();
    load_nat  (g_Qp_h, g_Qp_l, base,  128, k0, Ah, Al, tid);
    load_trans(g_S_h,  g_S_l,  sbase, 128, k0, Bh, Bl, tid);
    __syncthreads();
    mma_stage(Ah,Al,Bh,Bl,acc,wm,wn,lane);
  }
  size_t dbase = (size_t)b*TT + c*128;
#pragma unroll
  for(int mt=0;mt<2;mt++){
    int r0 = wm*32+mt*16+gid;
    float inv0 = 1.f / g_den[dbase + r0];
    float inv1 = 1.f / g_den[dbase + r0 + 8];
#pragma unroll
    for(int nt=0;nt<8;nt++){
      int col = wn*64+nt*8+tig*2;
      float* a = acc[mt][nt];
      bf2 lo;
      bf2 hi = split2(a[0]*inv0, a[1]*inv0, &lo);
      *(bf2*)&g_at_h[base + (size_t)r0*128+col] = hi;
      *(bf2*)&g_at_l[base + (size_t)r0*128+col] = lo;
      hi = split2(a[2]*inv1, a[3]*inv1, &lo);
      *(bf2*)&g_at_h[base + (size_t)(r0+8)*128+col] = hi;
      *(bf2*)&g_at_l[base + (size_t)(r0+8)*128+col] = lo;
    }
  }
}

// tokens = LN2(tokens + 0.1 * (attn @ Wo^T))   fused GEMM+residual+LN
__global__ void wo_ln2_kernel(int l, const float* __restrict__ w, const float* __restrict__ bia){
  GEMM_PRE();
  __shared__ float Ps[128][8], Qs[128][8];
  __shared__ float Mu[128], Rv[128];
  size_t abase = (size_t)blockIdx.x*128*128;
  size_t bbase = (size_t)l*16384;
  for(int k0=0;k0<128;k0+=16){
    __syncthreads();
    load_nat(g_at_h, g_at_l, abase, 128, k0, Ah, Al, tid);
    load_nat(g_Wo_h, g_Wo_l, bbase, 128, k0, Bh, Bl, tid);
    __syncthreads();
    mma_stage(Ah,Al,Bh,Bl,acc,wm,wn,lane);
  }
  int slot = wn*4 + tig;
  size_t row0 = (size_t)blockIdx.x*128;
#pragma unroll
  for(int mt=0;mt<2;mt++){
    int rl0 = wm*32+mt*16+gid;
    float s0=0.f,q0=0.f,s1=0.f,q1=0.f;
#pragma unroll
    for(int nt=0;nt<8;nt++){
      int col = wn*64+nt*8+tig*2;
      float* a = acc[mt][nt];
      float x0 = g_tokens[(row0+rl0)*128+col  ] + 0.1f*a[0];
      float x1 = g_tokens[(row0+rl0)*128+col+1] + 0.1f*a[1];
      float x2 = g_tokens[(row0+rl0+8)*128+col  ] + 0.1f*a[2];
      float x3 = g_tokens[(row0+rl0+8)*128+col+1] + 0.1f*a[3];
      a[0]=x0; a[1]=x1; a[2]=x2; a[3]=x3;
      s0 += x0+x1; q0 += x0*x0+x1*x1;
      s1 += x2+x3; q1 += x2*x2+x3*x3;
    }
    Ps[rl0][slot]=s0; Qs[rl0][slot]=q0;
    Ps[rl0+8][slot]=s1; Qs[rl0+8][slot]=q1;
  }
  __syncthreads();
  if(tid < 128){
    float s=0.f,q=0.f;
#pragma unroll
    for(int j=0;j<8;j++){ s+=Ps[tid][j]; q+=Qs[tid][j]; }
    float m = s*(1.f/128.f);
    float v = q*(1.f/128.f) - m*m;
    Mu[tid]=m; Rv[tid]=rsqrtf(v + 1e-5f);
  }
  __syncthreads();
#pragma unroll
  for(int mt=0;mt<2;mt++){
    int rl0 = wm*32+mt*16+gid;
    float m0=Mu[rl0], i0=Rv[rl0], m1=Mu[rl0+8], i1=Rv[rl0+8];
#pragma unroll
    for(int nt=0;nt<8;nt++){
      int col = wn*64+nt*8+tig*2;
      float* a = acc[mt][nt];
      float w0=w[col], w1=w[col+1], b0=bia[col], b1=bia[col+1];
      *(float2*)&g_tokens[(row0+rl0)*128+col] =
        make_float2((a[0]-m0)*i0*w0+b0, (a[1]-m0)*i0*w1+b1);
      *(float2*)&g_tokens[(row0+rl0+8)*128+col] =
        make_float2((a[2]-m1)*i1*w0+b0, (a[3]-m1)*i1*w1+b1);
    }
  }
}

// ----------------- launch -----------------
extern "C" void kernel_launch(void* const* d_in, const int* in_sizes, int n_in,
                              void* d_out, int out_size){
  const float* xs   = (const float*)d_in[0];
  const float* ys   = (const float*)d_in[1];
  const float* qx   = (const float*)d_in[2];
  const float* Wq   = (const float*)d_in[3];
  const float* Wk   = (const float*)d_in[4];
  const float* Wv   = (const float*)d_in[5];
  const float* Wgw  = (const float*)d_in[6];
  const float* Wgb  = (const float*)d_in[7];
  const float* Wo   = (const float*)d_in[8];
  const float* ln1w = (const float*)d_in[9];
  const float* ln1b = (const float*)d_in[10];
  const float* ln2w = (const float*)d_in[11];
  const float* ln2b = (const float*)d_in[12];
  const float* pw   = (const float*)d_in[13];
  float* out = (float*)d_out;

  build_wcat_k  <<<512, 256>>>(Wq, Wk, Wv, Wgw);
  build_wo_k    <<<128, 256>>>(Wo);
  build_tokens_k<<<4096,256>>>(xs, ys, qx);

  for(int l=0;l<2;l++){
    ln1_kernel   <<<dim3(TT,NB), 128>>>(ln1w + l*128, ln1b + l*128);
    proj_kernel  <<<dim3(64,4),  256>>>(l);
    act_kernel   <<<dim3(TT,NB), 128>>>(Wgb + l*128);
    ksum_kernel  <<<dim3(NC,NB), 128>>>();
    kv_kernel    <<<dim3(NC,NB), 256>>>();
    scan_kernel  <<<dim3(128,NB),128>>>();
    score_kernel <<<dim3(NC,NB), 256>>>();
    den_kernel   <<<dim3(TT,NB), 128>>>();
    num_kernel   <<<dim3(NC,NB), 256>>>();
    wo_ln2_kernel<<<64, 256>>>(l, ln2w + l*128, ln2b + l*128);
  }
  pred_kernel<<<NB, 128>>>(pw, out);
}

// round 3
// speedup vs baseline: 2.0109x; 1.3218x over previous
#include <cuda_runtime.h>
#include <cuda_bf16.h>
#include <math.h>

#define TT 4096
#define NB 2
#define NC 32
#define AKP 24   // smem row stride in halves

typedef __nv_bfloat16  bf;
typedef __nv_bfloat162 bf2;

// ----------------- static device scratch -----------------
__device__ __align__(16) float g_tokens[NB*TT*128];
__device__ __align__(16) float g_P[(size_t)NB*TT*512];
__device__ __align__(16) float g_KV[NB*NC*128*128];
__device__ __align__(16) float g_Ksum[NB*NC*128];
__device__ __align__(16) float g_KsumX[NB*NC*128];
__device__ __align__(16) float g_rs[NB*TT*2];

__device__ __align__(16) bf g_x_h [NB*TT*128], g_x_l [NB*TT*128];
__device__ __align__(16) bf g_Qp_h[NB*TT*128], g_Qp_l[NB*TT*128];
__device__ __align__(16) bf g_Kp_h[NB*TT*128], g_Kp_l[NB*TT*128];
__device__ __align__(16) bf g_Vg_h[NB*TT*128], g_Vg_l[NB*TT*128];
__device__ __align__(16) bf g_As_h[NB*TT*128], g_As_l[NB*TT*128];
__device__ __align__(16) bf g_S_h [NB*NC*128*128], g_S_l [NB*NC*128*128];
__device__ __align__(16) bf g_at_h[NB*TT*128], g_at_l[NB*TT*128];
__device__ __align__(16) bf g_Wc_h[2*512*128],  g_Wc_l[2*512*128];
__device__ __align__(16) bf g_Wo_h[2*128*128],  g_Wo_l[2*128*128];

// ----------------- helpers -----------------
__device__ __forceinline__ float phi_f(float x){ return x > 0.f ? x + 1.f : expf(x); }
__device__ __forceinline__ float sigm_f(float x){ return 1.f/(1.f+expf(-x)); }
__device__ __forceinline__ float bsum(bf h, bf l){ return __bfloat162float(h)+__bfloat162float(l); }

__device__ __forceinline__ void split1(float v, bf* H, bf* L){
  bf h = __float2bfloat16(v);
  *H = h; *L = __float2bfloat16(v - __bfloat162float(h));
}
__device__ __forceinline__ bf2 split2(float v0, float v1, bf2* lo){
  bf h0=__float2bfloat16(v0), h1=__float2bfloat16(v1);
  *lo = __halves2bfloat162(__float2bfloat16(v0-__bfloat162float(h0)),
                           __float2bfloat16(v1-__bfloat162float(h1)));
  return __halves2bfloat162(h0,h1);
}
__device__ __forceinline__ unsigned bits2(bf2 v){ return *(unsigned*)&v; }

__device__ __forceinline__ unsigned sptr(const void* p){
  return (unsigned)__cvta_generic_to_shared(p);
}
__device__ __forceinline__ void ldsm4(unsigned addr, unsigned* r){
  asm volatile("ldmatrix.sync.aligned.m8n8.x4.shared.b16 {%0,%1,%2,%3}, [%4];"
    : "=r"(r[0]),"=r"(r[1]),"=r"(r[2]),"=r"(r[3]) : "r"(addr));
}
__device__ __forceinline__ void mmab(float* c, const unsigned* a, unsigned b0, unsigned b1){
  asm volatile("mma.sync.aligned.m16n8k16.row.col.f32.bf16.bf16.f32 "
    "{%0,%1,%2,%3},{%4,%5,%6,%7},{%8,%9},{%0,%1,%2,%3};"
    : "+f"(c[0]),"+f"(c[1]),"+f"(c[2]),"+f"(c[3])
    : "r"(a[0]),"r"(a[1]),"r"(a[2]),"r"(a[3]),"r"(b0),"r"(b1));
}

__device__ __forceinline__ float warp_sum(float s){
#pragma unroll
  for(int o=16;o>0;o>>=1) s += __shfl_xor_sync(0xffffffffu, s, o);
  return s;
}
__device__ __forceinline__ float block_reduce1(float s){
#pragma unroll
  for(int o=16;o>0;o>>=1) s += __shfl_down_sync(0xffffffffu, s, o);
  __shared__ float rr[4];
  int w = threadIdx.x>>5;
  if((threadIdx.x&31)==0) rr[w]=s;
  __syncthreads();
  return rr[0]+rr[1]+rr[2]+rr[3];
}

// ---------- smem tile loaders (256 threads) ----------
// 128-row natural: gmem [row][k] -> smem [row][k16]
__device__ __forceinline__ void load_nat128(const bf* __restrict__ Gh, const bf* __restrict__ Gl,
                                            size_t base, int ldg, int k0,
                                            bf (*Sh)[AKP], bf (*Sl)[AKP], int tid){
  int r = tid>>1, q = (tid&1)<<3;
  size_t off = base + (size_t)r*ldg + k0 + q;
  *(uint4*)&Sh[r][q] = *(const uint4*)(Gh + off);
  *(uint4*)&Sl[r][q] = *(const uint4*)(Gl + off);
}
// 64-row natural (first 128 threads)
__device__ __forceinline__ void load_nat64(const bf* __restrict__ Gh, const bf* __restrict__ Gl,
                                           size_t base, int ldg, int k0,
                                           bf (*Sh)[AKP], bf (*Sl)[AKP], int tid){
  if(tid < 128){
    int r = tid>>1, q = (tid&1)<<3;
    size_t off = base + (size_t)r*ldg + k0 + q;
    *(uint4*)&Sh[r][q] = *(const uint4*)(Gh + off);
    *(uint4*)&Sl[r][q] = *(const uint4*)(Gl + off);
  }
}
// 128-row transpose: gmem [k][n] -> smem [n][k16]
__device__ __forceinline__ void load_trans128(const bf* __restrict__ Gh, const bf* __restrict__ Gl,
                                              size_t base, int ldg, int k0,
                                              bf (*Sh)[AKP], bf (*Sl)[AKP], int tid){
  int n = (tid&63)<<1, p0 = tid>>6;
#pragma unroll
  for(int p=p0;p<8;p+=4){
    int k = k0 + 2*p;
    size_t o0 = base + (size_t)k*ldg + n;
    bf2 h0 = *(const bf2*)(Gh + o0);
    bf2 h1 = *(const bf2*)(Gh + o0 + ldg);
    *(bf2*)&Sh[n  ][2*p] = __halves2bfloat162(h0.x, h1.x);
    *(bf2*)&Sh[n+1][2*p] = __halves2bfloat162(h0.y, h1.y);
    bf2 l0 = *(const bf2*)(Gl + o0);
    bf2 l1 = *(const bf2*)(Gl + o0 + ldg);
    *(bf2*)&Sl[n  ][2*p] = __halves2bfloat162(l0.x, l1.x);
    *(bf2*)&Sl[n+1][2*p] = __halves2bfloat162(l0.y, l1.y);
  }
}
// 64-row transpose
__device__ __forceinline__ void load_trans64(const bf* __restrict__ Gh, const bf* __restrict__ Gl,
                                             size_t base, int ldg, int k0,
                                             bf (*Sh)[AKP], bf (*Sl)[AKP], int tid){
  int n = (tid&31)<<1, p = tid>>5;   // p in 0..7
  int k = k0 + 2*p;
  size_t o0 = base + (size_t)k*ldg + n;
  bf2 h0 = *(const bf2*)(Gh + o0);
  bf2 h1 = *(const bf2*)(Gh + o0 + ldg);
  *(bf2*)&Sh[n  ][2*p] = __halves2bfloat162(h0.x, h1.x);
  *(bf2*)&Sh[n+1][2*p] = __halves2bfloat162(h0.y, h1.y);
  bf2 l0 = *(const bf2*)(Gl + o0);
  bf2 l1 = *(const bf2*)(Gl + o0 + ldg);
  *(bf2*)&Sl[n  ][2*p] = __halves2bfloat162(l0.x, l1.x);
  *(bf2*)&Sl[n+1][2*p] = __halves2bfloat162(l0.y, l1.y);
}

// ---------- one k16 stage of bf16x3 mma; warp tile = MT*16 x PN*16 ----------
template<int MT,int PN>
__device__ __forceinline__ void mma_stage(const bf (*AhS)[AKP], const bf (*AlS)[AKP],
                                          const bf (*BhS)[AKP], const bf (*BlS)[AKP],
                                          float (*acc)[2*PN][4], int wm, int wn, int lane){
  unsigned ah[MT][4], al[MT][4];
  int ar = lane & 15, ac = (lane & 16) >> 1;
#pragma unroll
  for(int mt=0;mt<MT;mt++){
    int r = wm*(MT*16) + mt*16 + ar;
    ldsm4(sptr(&AhS[r][ac]), ah[mt]);
    ldsm4(sptr(&AlS[r][ac]), al[mt]);
  }
  int br = (lane&7) + ((lane>>1)&8);
  int bc = lane & 8;
#pragma unroll
  for(int p=0;p<PN;p++){
    unsigned bh[4], bl[4];
    int n = wn*(PN*16) + p*16 + br;
    ldsm4(sptr(&BhS[n][bc]), bh);
    ldsm4(sptr(&BlS[n][bc]), bl);
#pragma unroll
    for(int mt=0;mt<MT;mt++){
      mmab(acc[mt][2*p  ], ah[mt], bh[0],bh[1]);
      mmab(acc[mt][2*p  ], al[mt], bh[0],bh[1]);
      mmab(acc[mt][2*p  ], ah[mt], bl[0],bl[1]);
      mmab(acc[mt][2*p+1], ah[mt], bh[2],bh[3]);
      mmab(acc[mt][2*p+1], al[mt], bh[2],bh[3]);
      mmab(acc[mt][2*p+1], ah[mt], bl[2],bl[3]);
    }
  }
}

#define GEMM_VARS(MT,PN) \
  __shared__ __align__(16) bf Ah[128][AKP], Al[128][AKP], Bh[128][AKP], Bl[128][AKP]; \
  int tid=threadIdx.x, lane=tid&31, wid=tid>>5, wm=wid>>1, wn=wid&1; \
  int gid=lane>>2, tig=lane&3; \
  float acc[MT][2*PN][4]; \
  _Pragma("unroll") for(int i_=0;i_<MT;i_++) _Pragma("unroll") for(int j_=0;j_<2*PN;j_++) \
    _Pragma("unroll") for(int k_=0;k_<4;k_++) acc[i_][j_][k_]=0.f;

// ----------------- setup: one merged kernel -----------------
__global__ void build_all(const float* __restrict__ xs, const float* __restrict__ ys,
                          const float* __restrict__ qx,
                          const float* __restrict__ Wq, const float* __restrict__ Wk,
                          const float* __restrict__ Wv, const float* __restrict__ Wg,
                          const float* __restrict__ Wo){
  int bid = blockIdx.x;
  if(bid < 4096){
    int idx = bid*256 + threadIdx.x;            // NB*TT*128
    int b = idx >> 19;
    int r = idx & ((1<<19)-1);
    int t = r >> 7, d = r & 127;
    float v;
    if(t < 4095) v = (d < 127) ? xs[((size_t)b*4095 + t)*127 + d] : ys[(size_t)b*4095 + t];
    else         v = (d < 127) ? qx[(size_t)b*127 + d] : 0.f;
    g_tokens[idx] = v;
  }else if(bid < 4608){
    int idx = (bid-4096)*256 + threadIdx.x;     // 2*512*128
    int l = idx >> 16;
    int r = idx & ((1<<16)-1);
    int n = r >> 7, k = r & 127;
    float v = 0.f;
    if(n < 127)        v = Wq[((size_t)l*127 + n)*128 + k];
    else if(n == 127)  v = 0.f;
    else if(n < 255)   v = Wk[((size_t)l*127 + (n-128))*128 + k];
    else if(n == 255)  v = 0.f;
    else if(n < 384)   v = Wv[((size_t)l*128 + (n-256))*128 + k];
    else               v = Wg[((size_t)l*128 + (n-384))*128 + k];
    split1(v, &g_Wc_h[idx], &g_Wc_l[idx]);
  }else{
    int idx = (bid-4608)*256 + threadIdx.x;     // 2*128*128
    split1(Wo[idx], &g_Wo_h[idx], &g_Wo_l[idx]);
  }
}

// ----------------- elementwise (warp-per-token) -----------------
__global__ void ln1_kernel(const float* __restrict__ w, const float* __restrict__ bia){
  int warp = threadIdx.x>>5, lane = threadIdx.x&31;
  int t = blockIdx.x*4 + warp, b = blockIdx.y;
  size_t idx = ((size_t)b*TT + t)*128 + lane*4;
  float4 x = *(const float4*)&g_tokens[idx];
  float s = warp_sum(x.x+x.y+x.z+x.w);
  float q = warp_sum(x.x*x.x+x.y*x.y+x.z*x.z+x.w*x.w);
  float m = s*(1.f/128.f);
  float inv = rsqrtf(q*(1.f/128.f) - m*m + 1e-5f);
  float4 wv = *(const float4*)&w[lane*4];
  float4 bv = *(const float4*)&bia[lane*4];
  float o0=(x.x-m)*inv*wv.x+bv.x, o1=(x.y-m)*inv*wv.y+bv.y;
  float o2=(x.z-m)*inv*wv.z+bv.z, o3=(x.w-m)*inv*wv.w+bv.w;
  bf2 l0,l1; bf2 h0=split2(o0,o1,&l0), h1=split2(o2,o3,&l1);
  *(uint2*)&g_x_h[idx] = make_uint2(bits2(h0), bits2(h1));
  *(uint2*)&g_x_l[idx] = make_uint2(bits2(l0), bits2(l1));
}

__global__ void act_kernel(const float* __restrict__ gb){
  int warp = threadIdx.x>>5, lane = threadIdx.x&31;
  int t = blockIdx.x*4 + warp, b = blockIdx.y;
  size_t bt = (size_t)b*TT + t;
  const float* p = g_P + bt*512;
  float4 q = *(const float4*)(p + lane*4);
  float4 k = *(const float4*)(p + 128 + lane*4);
  float4 v = *(const float4*)(p + 256 + lane*4);
  float4 g = *(const float4*)(p + 384 + lane*4);
  float4 gv = *(const float4*)(gb + lane*4);
  float qp0=phi_f(q.x), qp1=phi_f(q.y), qp2=phi_f(q.z), qp3=phi_f(q.w);
  float kp0=phi_f(k.x), kp1=phi_f(k.y), kp2=phi_f(k.z), kp3=phi_f(k.w);
  if(lane==31){ qp3=0.f; kp3=0.f; }   // h=127 padding
  float vg0=v.x*sigm_f(g.x+gv.x), vg1=v.y*sigm_f(g.y+gv.y);
  float vg2=v.z*sigm_f(g.z+gv.z), vg3=v.w*sigm_f(g.w+gv.w);
  size_t o = bt*128 + lane*4;
  bf2 lo0,lo1,hi0,hi1;
  hi0=split2(qp0,qp1,&lo0); hi1=split2(qp2,qp3,&lo1);
  *(uint2*)&g_Qp_h[o]=make_uint2(bits2(hi0),bits2(hi1));
  *(uint2*)&g_Qp_l[o]=make_uint2(bits2(lo0),bits2(lo1));
  hi0=split2(kp0,kp1,&lo0); hi1=split2(kp2,kp3,&lo1);
  *(uint2*)&g_Kp_h[o]=make_uint2(bits2(hi0),bits2(hi1));
  *(uint2*)&g_Kp_l[o]=make_uint2(bits2(lo0),bits2(lo1));
  hi0=split2(vg0,vg1,&lo0); hi1=split2(vg2,vg3,&lo1);
  *(uint2*)&g_Vg_h[o]=make_uint2(bits2(hi0),bits2(hi1));
  *(uint2*)&g_Vg_l[o]=make_uint2(bits2(lo0),bits2(lo1));
}

// ----------------- GEMMs -----------------
// P[8192x512] = x @ Wcat^T     grid (64,4)
__global__ void proj_kernel(int l){
  GEMM_VARS(2,4);
  size_t abase = (size_t)blockIdx.x*128*128;
  size_t bbase = ((size_t)l*512 + blockIdx.y*128)*128;
  for(int k0=0;k0<128;k0+=16){
    __syncthreads();
    load_nat128(g_x_h,  g_x_l,  abase, 128, k0, Ah, Al, tid);
    load_nat128(g_Wc_h, g_Wc_l, bbase, 128, k0, Bh, Bl, tid);
    __syncthreads();
    mma_stage<2,4>(Ah,Al,Bh,Bl,acc,wm,wn,lane);
  }
  float* C = g_P + (size_t)blockIdx.x*128*512 + blockIdx.y*128;
#pragma unroll
  for(int mt=0;mt<2;mt++){
    int r0 = wm*32+mt*16+gid;
#pragma unroll
    for(int nt=0;nt<8;nt++){
      int col = wn*64+nt*8+tig*2;
      float* a = acc[mt][nt];
      *(float2*)&C[(size_t)r0*512+col]     = make_float2(a[0],a[1]);
      *(float2*)&C[(size_t)(r0+8)*512+col] = make_float2(a[2],a[3]);
    }
  }
}

// KV[h][m-half] = sum_t Kp[t][h]*Vg[t][m], plus Ksum on z==0.  grid (NC,NB,2)
__global__ void kv_kernel(){
  GEMM_VARS(2,2);
  int c=blockIdx.x, b=blockIdx.y, z=blockIdx.z;
  size_t base = ((size_t)b*TT + c*128)*128;
  float ks = 0.f;
  for(int k0=0;k0<128;k0+=16){
    __syncthreads();
    load_trans128(g_Kp_h, g_Kp_l, base, 128, k0, Ah, Al, tid);
    load_trans64 (g_Vg_h, g_Vg_l, base + z*64, 128, k0, Bh, Bl, tid);
    __syncthreads();
    mma_stage<2,2>(Ah,Al,Bh,Bl,acc,wm,wn,lane);
    if(z==0 && tid<128){
#pragma unroll
      for(int k=0;k<16;k++) ks += bsum(Ah[tid][k], Al[tid][k]);
    }
  }
  float* C = g_KV + (size_t)(b*NC + c)*16384 + z*64;
#pragma unroll
  for(int mt=0;mt<2;mt++){
    int r0 = wm*32+mt*16+gid;
#pragma unroll
    for(int nt=0;nt<4;nt++){
      int col = wn*32+nt*8+tig*2;
      float* a = acc[mt][nt];
      *(float2*)&C[(size_t)r0*128+col]     = make_float2(a[0],a[1]);
      *(float2*)&C[(size_t)(r0+8)*128+col] = make_float2(a[2],a[3]);
    }
  }
  if(z==0 && tid<128) g_Ksum[(size_t)(b*NC + c)*128 + tid] = ks;
}

// register-resident prefix over chunks.  grid (128,NB), block 128
__global__ void scan_kernel(){
  int h=blockIdx.x, b=blockIdx.y, m=threadIdx.x;
  size_t rowbase = (((size_t)b*NC)*128 + h)*128 + m;
  float acc = 0.f;
#pragma unroll
  for(int c=0;c<NC;c++){
    size_t i = rowbase + (size_t)c*16384;
    bf hh = __float2bfloat16(acc);
    g_S_h[i] = hh;
    g_S_l[i] = __float2bfloat16(acc - __bfloat162float(hh));
    acc += g_KV[i];
  }
  if(m==0){
    float ks=0.f;
    for(int c=0;c<NC;c++){
      size_t j = (size_t)(b*NC + c)*128 + h;
      g_KsumX[j] = ks;
      ks += g_Ksum[j];
    }
  }
}

// A[t][s-half] = tril(Qp @ Kp^T), + partial row sums.  grid (NC,NB,2)
__global__ void score_kernel(){
  GEMM_VARS(2,2);
  __shared__ float rs2[128][2];
  int c=blockIdx.x, b=blockIdx.y, z=blockIdx.z;
  size_t base = ((size_t)b*TT + c*128)*128;
  for(int k0=0;k0<128;k0+=16){
    __syncthreads();
    load_nat128(g_Qp_h, g_Qp_l, base, 128, k0, Ah, Al, tid);
    load_nat64 (g_Kp_h, g_Kp_l, base + (size_t)(z*64)*128, 128, k0, Bh, Bl, tid);
    __syncthreads();
    mma_stage<2,2>(Ah,Al,Bh,Bl,acc,wm,wn,lane);
  }
#pragma unroll
  for(int mt=0;mt<2;mt++){
    int r0 = wm*32+mt*16+gid;
    float s0=0.f, s1=0.f;
#pragma unroll
    for(int nt=0;nt<4;nt++){
      int col = z*64 + wn*32 + nt*8 + tig*2;
      float* a = acc[mt][nt];
      float v0 = (col   <= r0  )? a[0] : 0.f;
      float v1 = (col+1 <= r0  )? a[1] : 0.f;
      float v2 = (col   <= r0+8)? a[2] : 0.f;
      float v3 = (col+1 <= r0+8)? a[3] : 0.f;
      s0 += v0+v1; s1 += v2+v3;
      bf2 lo;
      bf2 hi = split2(v0,v1,&lo);
      *(bf2*)&g_As_h[base + (size_t)r0*128+col] = hi;
      *(bf2*)&g_As_l[base + (size_t)r0*128+col] = lo;
      hi = split2(v2,v3,&lo);
      *(bf2*)&g_As_h[base + (size_t)(r0+8)*128+col] = hi;
      *(bf2*)&g_As_l[base + (size_t)(r0+8)*128+col] = lo;
    }
    // reduce over the 4 lanes (tig) sharing this row-pair
    s0 += __shfl_xor_sync(0xffffffffu, s0, 1); s0 += __shfl_xor_sync(0xffffffffu, s0, 2);
    s1 += __shfl_xor_sync(0xffffffffu, s1, 1); s1 += __shfl_xor_sync(0xffffffffu, s1, 2);
    if(tig==0){ rs2[r0][wn]=s0; rs2[r0+8][wn]=s1; }
  }
  __syncthreads();
  if(tid<128)
    g_rs[((size_t)b*TT + c*128 + tid)*2 + z] = rs2[tid][0] + rs2[tid][1];
}

// attn[t][m-half] = (A@Vg + Qp@S) / den, den computed inline.  grid (NC,NB,2)
__global__ void num_kernel(){
  GEMM_VARS(2,2);
  __shared__ float kx[128], dsm[128];
  int c=blockIdx.x, b=blockIdx.y, z=blockIdx.z;
  size_t base  = ((size_t)b*TT + c*128)*128;
  size_t sbase = (size_t)(b*NC + c)*16384;
  if(tid<128) kx[tid] = g_KsumX[(size_t)(b*NC + c)*128 + tid];
  for(int k0=0;k0<128;k0+=16){
    __syncthreads();
    load_nat128 (g_As_h, g_As_l, base, 128, k0, Ah, Al, tid);
    load_trans64(g_Vg_h, g_Vg_l, base + z*64, 128, k0, Bh, Bl, tid);
    __syncthreads();
    mma_stage<2,2>(Ah,Al,Bh,Bl,acc,wm,wn,lane);
  }
  float dd = 0.f;
  for(int k0=0;k0<128;k0+=16){
    __syncthreads();
    load_nat128 (g_Qp_h, g_Qp_l, base,  128, k0, Ah, Al, tid);
    load_trans64(g_S_h,  g_S_l,  sbase + z*64, 128, k0, Bh, Bl, tid);
    __syncthreads();
    mma_stage<2,2>(Ah,Al,Bh,Bl,acc,wm,wn,lane);
    if(tid<128){
#pragma unroll
      for(int k=0;k<16;k++) dd += bsum(Ah[tid][k], Al[tid][k]) * kx[k0+k];
    }
  }
  if(tid<128){
    size_t bt2 = ((size_t)b*TT + c*128 + tid)*2;
    dsm[tid] = fmaxf(g_rs[bt2] + g_rs[bt2+1] + dd, 1e-6f);
  }
  __syncthreads();
#pragma unroll
  for(int mt=0;mt<2;mt++){
    int r0 = wm*32+mt*16+gid;
    float inv0 = 1.f/dsm[r0], inv1 = 1.f/dsm[r0+8];
#pragma unroll
    for(int nt=0;nt<4;nt++){
      int col = z*64 + wn*32 + nt*8 + tig*2;
      float* a = acc[mt][nt];
      bf2 lo;
      bf2 hi = split2(a[0]*inv0, a[1]*inv0, &lo);
      *(bf2*)&g_at_h[base + (size_t)r0*128+col] = hi;
      *(bf2*)&g_at_l[base + (size_t)r0*128+col] = lo;
      hi = split2(a[2]*inv1, a[3]*inv1, &lo);
      *(bf2*)&g_at_h[base + (size_t)(r0+8)*128+col] = hi;
      *(bf2*)&g_at_l[base + (size_t)(r0+8)*128+col] = lo;
    }
  }
}

// tokens = LN2(tokens + 0.1*(attn @ Wo^T)).  grid 128, 64-row tiles
__global__ void wo_ln2_kernel(int l, const float* __restrict__ w, const float* __restrict__ bia){
  GEMM_VARS(1,4);
  __shared__ float Ps[64][8], Qs[64][8];
  __shared__ float Mu[64], Rv[64];
  size_t abase = (size_t)blockIdx.x*64*128;
  size_t bbase = (size_t)l*16384;
  for(int k0=0;k0<128;k0+=16){
    __syncthreads();
    load_nat64 (g_at_h, g_at_l, abase, 128, k0, Ah, Al, tid);
    load_nat128(g_Wo_h, g_Wo_l, bbase, 128, k0, Bh, Bl, tid);
    __syncthreads();
    mma_stage<1,4>(Ah,Al,Bh,Bl,acc,wm,wn,lane);
  }
  int slot = wn*4 + tig;
  size_t row0 = (size_t)blockIdx.x*64;
  {
    int rl0 = wm*16+gid;
    float s0=0.f,q0=0.f,s1=0.f,q1=0.f;
#pragma unroll
    for(int nt=0;nt<8;nt++){
      int col = wn*64+nt*8+tig*2;
      float* a = acc[0][nt];
      float x0 = g_tokens[(row0+rl0)*128+col  ] + 0.1f*a[0];
      float x1 = g_tokens[(row0+rl0)*128+col+1] + 0.1f*a[1];
      float x2 = g_tokens[(row0+rl0+8)*128+col  ] + 0.1f*a[2];
      float x3 = g_tokens[(row0+rl0+8)*128+col+1] + 0.1f*a[3];
      a[0]=x0; a[1]=x1; a[2]=x2; a[3]=x3;
      s0 += x0+x1; q0 += x0*x0+x1*x1;
      s1 += x2+x3; q1 += x2*x2+x3*x3;
    }
    Ps[rl0][slot]=s0; Qs[rl0][slot]=q0;
    Ps[rl0+8][slot]=s1; Qs[rl0+8][slot]=q1;
  }
  __syncthreads();
  if(tid < 64){
    float s=0.f,q=0.f;
#pragma unroll
    for(int j=0;j<8;j++){ s+=Ps[tid][j]; q+=Qs[tid][j]; }
    float m = s*(1.f/128.f);
    float v = q*(1.f/128.f) - m*m;
    Mu[tid]=m; Rv[tid]=rsqrtf(v + 1e-5f);
  }
  __syncthreads();
  {
    int rl0 = wm*16+gid;
    float m0=Mu[rl0], i0=Rv[rl0], m1=Mu[rl0+8], i1=Rv[rl0+8];
#pragma unroll
    for(int nt=0;nt<8;nt++){
      int col = wn*64+nt*8+tig*2;
      float* a = acc[0][nt];
      float w0=w[col], w1=w[col+1], b0=bia[col], b1=bia[col+1];
      *(float2*)&g_tokens[(row0+rl0)*128+col] =
        make_float2((a[0]-m0)*i0*w0+b0, (a[1]-m0)*i0*w1+b1);
      *(float2*)&g_tokens[(row0+rl0+8)*128+col] =
        make_float2((a[2]-m1)*i1*w0+b0, (a[3]-m1)*i1*w1+b1);
    }
  }
}

__global__ void pred_kernel(const float* __restrict__ pw, float* __restrict__ out){
  int b = blockIdx.x, h = threadIdx.x;
  float v = g_tokens[((size_t)b*TT + (TT-1))*128 + h] * pw[h];
  float tot = block_reduce1(v);
  if(h == 0) out[b] = tot;
}

// ----------------- launch -----------------
extern "C" void kernel_launch(void* const* d_in, const int* in_sizes, int n_in,
                              void* d_out, int out_size){
  const float* xs   = (const float*)d_in[0];
  const float* ys   = (const float*)d_in[1];
  const float* qx   = (const float*)d_in[2];
  const float* Wq   = (const float*)d_in[3];
  const float* Wk   = (const float*)d_in[4];
  const float* Wv   = (const float*)d_in[5];
  const float* Wgw  = (const float*)d_in[6];
  const float* Wgb  = (const float*)d_in[7];
  const float* Wo   = (const float*)d_in[8];
  const float* ln1w = (const float*)d_in[9];
  const float* ln1b = (const float*)d_in[10];
  const float* ln2w = (const float*)d_in[11];
  const float* ln2b = (const float*)d_in[12];
  const float* pw   = (const float*)d_in[13];
  float* out = (float*)d_out;

  build_all<<<4736, 256>>>(xs, ys, qx, Wq, Wk, Wv, Wgw, Wo);

  for(int l=0;l<2;l++){
    ln1_kernel   <<<dim3(TT/4,NB), 128>>>(ln1w + l*128, ln1b + l*128);
    proj_kernel  <<<dim3(64,4),    256>>>(l);
    act_kernel   <<<dim3(TT/4,NB), 128>>>(Wgb + l*128);
    kv_kernel    <<<dim3(NC,NB,2), 256>>>();
    scan_kernel  <<<dim3(128,NB),  128>>>();
    score_kernel <<<dim3(NC,NB,2), 256>>>();
    num_kernel   <<<dim3(NC,NB,2), 256>>>();
    wo_ln2_kernel<<<128, 256>>>(l, ln2w + l*128, ln2b + l*128);
  }
  pred_kernel<<<NB, 128>>>(pw, out);
}